// round 2
// baseline (speedup 1.0000x reference)
#include <cuda_runtime.h>

// ROIAlign / crop_and_resize (bilinear, extrapolation_value = 0)
// feature_map: [8, 64, 64, 256] f32 (B,H,W,C), rois: [8,128,4] f32
// out: [1024, 14, 14, 256] f32
//
// Two-phase: precompute per-pixel gather offsets + bilinear weights (1 thread
// per pixel), then a lean gather/FMA/store kernel (64 lanes x float4 per pixel).

#define B 8
#define H 64
#define W 64
#define C 256
#define NUM_ROIS 128
#define N_TOTAL (B * NUM_ROIS)             // 1024
#define CROP 14
#define PIX_PER_ROI (CROP * CROP)          // 196
#define TOTAL_PIX (N_TOTAL * PIX_PER_ROI)  // 200704
#define PIX_PER_BLOCK 4

// Scratch (allocation-free: __device__ globals)
__device__ int4   g_offs[TOTAL_PIX];   // byte offsets of tl,tr,bl,br rows (channel 0)
__device__ float4 g_wts[TOTAL_PIX];    // w_tl, w_tr, w_bl, w_br (all 0 if invalid)

__global__ __launch_bounds__(256) void roialign_precompute(
    const float* __restrict__ rois)
{
    const int pix = blockIdx.x * 256 + threadIdx.x;
    if (pix >= TOTAL_PIX) return;

    const int n   = pix / PIX_PER_ROI;
    const int rem = pix - n * PIX_PER_ROI;
    const int i   = rem / CROP;
    const int j   = rem - i * CROP;
    const int b   = n >> 7;

    const float4 r = __ldg((const float4*)(rois + n * 4));
    const float y1 = r.x, x1 = r.y, y2 = r.z, x2 = r.w;

    const float h_scale = (y2 - y1) * (float)(H - 1) / (float)(CROP - 1);
    const float w_scale = (x2 - x1) * (float)(W - 1) / (float)(CROP - 1);
    const float in_y = fmaf((float)i, h_scale, y1 * (float)(H - 1));
    const float in_x = fmaf((float)j, w_scale, x1 * (float)(W - 1));

    const bool valid = (in_y >= 0.f) && (in_y <= (float)(H - 1)) &&
                       (in_x >= 0.f) && (in_x <= (float)(W - 1));

    const float fy = floorf(in_y);
    const float fx = floorf(in_x);
    const float yl = in_y - fy;
    const float xl = in_x - fx;

    int ty = min(max((int)fy, 0), H - 1);
    int by = min(max((int)ceilf(in_y), 0), H - 1);
    int lx = min(max((int)fx, 0), W - 1);
    int rx = min(max((int)ceilf(in_x), 0), W - 1);

    float wtl = (1.f - xl) * (1.f - yl);
    float wtr = xl * (1.f - yl);
    float wbl = (1.f - xl) * yl;
    float wbr = xl * yl;
    if (!valid) {
        wtl = wtr = wbl = wbr = 0.f;
        ty = by = lx = rx = 0;
    }

    const int base = b * (H * W * C);
    int4 offs;
    offs.x = (base + (ty * W + lx) * C) * 4;   // byte offsets
    offs.y = (base + (ty * W + rx) * C) * 4;
    offs.z = (base + (by * W + lx) * C) * 4;
    offs.w = (base + (by * W + rx) * C) * 4;

    g_offs[pix] = offs;
    g_wts[pix]  = make_float4(wtl, wtr, wbl, wbr);
}

__global__ __launch_bounds__(256) void roialign_main(
    const float* __restrict__ fm,
    float* __restrict__ out)
{
    const int lane = threadIdx.x & 63;        // channel group (4 floats each)
    const int sub  = threadIdx.x >> 6;        // pixel within block
    const int pix  = blockIdx.x * PIX_PER_BLOCK + sub;

    const int4   offs = g_offs[pix];          // uniform across the 64 lanes
    const float4 w    = g_wts[pix];

    const char* fmb = (const char*)fm;
    const int   cb  = lane * 16;

    const float4 tl = *(const float4*)(fmb + offs.x + cb);
    const float4 tr = *(const float4*)(fmb + offs.y + cb);
    const float4 bl = *(const float4*)(fmb + offs.z + cb);
    const float4 br = *(const float4*)(fmb + offs.w + cb);

    float4 o;
    o.x = fmaf(tl.x, w.x, fmaf(tr.x, w.y, fmaf(bl.x, w.z, br.x * w.w)));
    o.y = fmaf(tl.y, w.x, fmaf(tr.y, w.y, fmaf(bl.y, w.z, br.y * w.w)));
    o.z = fmaf(tl.z, w.x, fmaf(tr.z, w.y, fmaf(bl.z, w.z, br.z * w.w)));
    o.w = fmaf(tl.w, w.x, fmaf(tr.w, w.y, fmaf(bl.w, w.z, br.w * w.w)));

    *(float4*)(out + (size_t)pix * C + lane * 4) = o;
}

extern "C" void kernel_launch(void* const* d_in, const int* in_sizes, int n_in,
                              void* d_out, int out_size)
{
    const float* fm   = (const float*)d_in[0];
    const float* rois = (const float*)d_in[1];
    float* out = (float*)d_out;

    roialign_precompute<<<(TOTAL_PIX + 255) / 256, 256>>>(rois);
    roialign_main<<<TOTAL_PIX / PIX_PER_BLOCK, 256>>>(fm, out);
}

// round 3
// speedup vs baseline: 1.3219x; 1.3219x over previous
#include <cuda_runtime.h>

// ROIAlign / crop_and_resize (bilinear, extrapolation_value = 0)
// feature_map: [8, 64, 64, 256] f32 (B,H,W,C), rois: [8,128,4] f32
// out: [1024, 14, 14, 256] f32
//
// One warp per output pixel. Lane covers channels [lane*4, lane*4+4) and
// [128+lane*4, 128+lane*4+4): 8 independent gather LDG.128 per thread,
// 2 streaming STG.128. Pixel params computed per-lane (warp-redundant, cheap).

#define B 8
#define H 64
#define W 64
#define C 256
#define NUM_ROIS 128
#define CROP 14
#define PIX_PER_ROI (CROP * CROP)          // 196
#define TOTAL_PIX (B * NUM_ROIS * PIX_PER_ROI)  // 200704
#define WARPS_PER_BLOCK 8

__global__ __launch_bounds__(256) void roialign_kernel(
    const float* __restrict__ fm,
    const float* __restrict__ rois,
    float* __restrict__ out)
{
    const int lane = threadIdx.x & 31;
    const int wid  = threadIdx.x >> 5;
    const int pix  = blockIdx.x * WARPS_PER_BLOCK + wid;

    // Decompose pixel id (warp-uniform values)
    const int n   = pix / PIX_PER_ROI;
    const int rem = pix - n * PIX_PER_ROI;
    const int i   = rem / CROP;
    const int j   = rem - i * CROP;
    const int b   = n >> 7;

    // ROI coords: all 32 lanes load same 16B (1 wavefront, broadcast)
    const float4 r = __ldg((const float4*)(rois + n * 4));
    const float y1 = r.x, x1 = r.y, y2 = r.z, x2 = r.w;

    const float h_scale = (y2 - y1) * (float)(H - 1) / (float)(CROP - 1);
    const float w_scale = (x2 - x1) * (float)(W - 1) / (float)(CROP - 1);
    const float in_y = fmaf((float)i, h_scale, y1 * (float)(H - 1));
    const float in_x = fmaf((float)j, w_scale, x1 * (float)(W - 1));

    const bool valid = (in_y >= 0.f) && (in_y <= (float)(H - 1)) &&
                       (in_x >= 0.f) && (in_x <= (float)(W - 1));

    const float fy = floorf(in_y);
    const float fx = floorf(in_x);
    const float yl = in_y - fy;
    const float xl = in_x - fx;

    int ty = min(max((int)fy, 0), H - 1);
    int by = min(max((int)ceilf(in_y), 0), H - 1);
    int lx = min(max((int)fx, 0), W - 1);
    int rx = min(max((int)ceilf(in_x), 0), W - 1);

    // Bilinear weights; zero them when invalid (output becomes exact 0)
    float wtl = (1.f - xl) * (1.f - yl);
    float wtr = xl * (1.f - yl);
    float wbl = (1.f - xl) * yl;
    float wbr = xl * yl;
    if (!valid) { wtl = wtr = wbl = wbr = 0.f; ty = by = lx = rx = 0; }

    const size_t base = (size_t)b * (H * W * C);
    const float* ptl = fm + base + (size_t)(ty * W + lx) * C + lane * 4;
    const float* ptr_ = fm + base + (size_t)(ty * W + rx) * C + lane * 4;
    const float* pbl = fm + base + (size_t)(by * W + lx) * C + lane * 4;
    const float* pbr = fm + base + (size_t)(by * W + rx) * C + lane * 4;

    // 8 independent gathers (two 128-channel halves), all issued up front
    const float4 tl0 = __ldg((const float4*)(ptl));
    const float4 tr0 = __ldg((const float4*)(ptr_));
    const float4 bl0 = __ldg((const float4*)(pbl));
    const float4 br0 = __ldg((const float4*)(pbr));
    const float4 tl1 = __ldg((const float4*)(ptl + 128));
    const float4 tr1 = __ldg((const float4*)(ptr_ + 128));
    const float4 bl1 = __ldg((const float4*)(pbl + 128));
    const float4 br1 = __ldg((const float4*)(pbr + 128));

    float4 o0, o1;
    o0.x = fmaf(tl0.x, wtl, fmaf(tr0.x, wtr, fmaf(bl0.x, wbl, br0.x * wbr)));
    o0.y = fmaf(tl0.y, wtl, fmaf(tr0.y, wtr, fmaf(bl0.y, wbl, br0.y * wbr)));
    o0.z = fmaf(tl0.z, wtl, fmaf(tr0.z, wtr, fmaf(bl0.z, wbl, br0.z * wbr)));
    o0.w = fmaf(tl0.w, wtl, fmaf(tr0.w, wtr, fmaf(bl0.w, wbl, br0.w * wbr)));
    o1.x = fmaf(tl1.x, wtl, fmaf(tr1.x, wtr, fmaf(bl1.x, wbl, br1.x * wbr)));
    o1.y = fmaf(tl1.y, wtl, fmaf(tr1.y, wtr, fmaf(bl1.y, wbl, br1.y * wbr)));
    o1.z = fmaf(tl1.z, wtl, fmaf(tr1.z, wtr, fmaf(bl1.z, wbl, br1.z * wbr)));
    o1.w = fmaf(tl1.w, wtl, fmaf(tr1.w, wtr, fmaf(bl1.w, wbl, br1.w * wbr)));

    // Streaming stores (evict-first): output is never re-read; keep L1 for fm
    float* op = out + (size_t)pix * C + lane * 4;
    __stcs((float4*)op, o0);
    __stcs((float4*)(op + 128), o1);
}

extern "C" void kernel_launch(void* const* d_in, const int* in_sizes, int n_in,
                              void* d_out, int out_size)
{
    const float* fm   = (const float*)d_in[0];
    const float* rois = (const float*)d_in[1];
    float* out = (float*)d_out;

    roialign_kernel<<<TOTAL_PIX / WARPS_PER_BLOCK, 256>>>(fm, rois, out);
}